// round 14
// baseline (speedup 1.0000x reference)
#include <cuda_runtime.h>
#include <cuda_bf16.h>
#include <cstdint>

#define GN 16
#define GQ 4096
#define GC 77
#define GD 512
#define GDC 768
#define GH 8
#define GS 64
#define GM (GN * GQ)  // 65536

// ---------------- scratch (device globals, allocation-free) ----------------
__device__ float g_att[(size_t)GM * GD];                 // attn output (fp32)
__device__ __nv_bfloat16 g_qhi[(size_t)GM * GD];         // q pre-split (scaled)
__device__ __nv_bfloat16 g_qlo[(size_t)GM * GD];
__device__ __nv_bfloat16 g_khi[(size_t)GN * GC * GD];    // k pre-split
__device__ __nv_bfloat16 g_klo[(size_t)GN * GC * GD];
__device__ __nv_bfloat16 g_vThi[(size_t)GN * GH * 64 * 80];  // V^T pre-split, c pad 80
__device__ __nv_bfloat16 g_vTlo[(size_t)GN * GH * 64 * 80];
__device__ __nv_bfloat16 g_wqT_hi[GD * GD], g_wqT_lo[GD * GD];
__device__ __nv_bfloat16 g_woT_hi[GD * GD], g_woT_lo[GD * GD];

__device__ __forceinline__ uint32_t smem_u32(const void* p) {
    uint32_t a;
    asm("{ .reg .u64 t; cvta.to.shared.u64 t, %1; cvt.u32.u64 %0, t; }"
        : "=r"(a) : "l"(p));
    return a;
}
__device__ __forceinline__ void cp_async16(uint32_t dst, const void* src) {
    asm volatile("cp.async.cg.shared.global [%0], [%1], 16;"
                 :: "r"(dst), "l"(src) : "memory");
}
#define CP_COMMIT() asm volatile("cp.async.commit_group;" ::: "memory")

__device__ __forceinline__ void ldm_x4(uint32_t (&f)[4], uint32_t addr) {
    asm volatile("ldmatrix.sync.aligned.m8n8.x4.shared.b16 {%0,%1,%2,%3}, [%4];"
                 : "=r"(f[0]), "=r"(f[1]), "=r"(f[2]), "=r"(f[3]) : "r"(addr));
}
__device__ __forceinline__ void mma16816(float (&d)[4], const uint32_t (&a)[4],
                                         uint32_t b0, uint32_t b1) {
    asm volatile(
        "mma.sync.aligned.m16n8k16.row.col.f32.bf16.bf16.f32 "
        "{%0,%1,%2,%3}, {%4,%5,%6,%7}, {%8,%9}, {%0,%1,%2,%3};"
        : "+f"(d[0]), "+f"(d[1]), "+f"(d[2]), "+f"(d[3])
        : "r"(a[0]), "r"(a[1]), "r"(a[2]), "r"(a[3]), "r"(b0), "r"(b1));
}

__device__ __forceinline__ void split_bf16(float x, __nv_bfloat16& hi, __nv_bfloat16& lo) {
    hi = __float2bfloat16_rn(x);
    lo = __float2bfloat16_rn(x - __bfloat162float(hi));
}

// ---------------------------------------------------------------------------
// bf16x3 mma.sync GEMM, 512 threads (16 warps, 32x32 warp tiles).
// Same 128x128 block tile, same smem layout/staging, same inner-loop term
// order (hi*hi, hi*lo, lo*hi with combined bfh/bfl loads) as the R6 golden
// kernel — only the warp-to-tile partition changed (more warps, fewer regs).
// NO __launch_bounds__ minBlocks (R9 proved it miscompiles via forced spill).
// ---------------------------------------------------------------------------
#define LDT 40
#define TILE_B (128 * LDT)
#define TILE_BYTES (TILE_B * 2)
#define STAGE_BYTES (4 * TILE_BYTES)
#define GEMM_SMEM (2 * STAGE_BYTES)   // 81920 B

template <bool HAS_BIAS, bool OUT_SPLIT>
__global__ __launch_bounds__(512) void gemm_mma3f(
    const float* __restrict__ A,
    const __nv_bfloat16* __restrict__ Bhi, const __nv_bfloat16* __restrict__ Blo,
    const float* __restrict__ bias, float* __restrict__ C,
    __nv_bfloat16* __restrict__ Chi, __nv_bfloat16* __restrict__ Clo,
    int M, int N, int K)
{
    extern __shared__ __align__(16) char gsm[];
    const uint32_t sa = smem_u32(gsm);

    const int tid = threadIdx.x;
    const int wid = tid >> 5, lane = tid & 31;
    const int warp_m = wid & 3;       // 4 x 32 rows
    const int warp_n = wid >> 2;      // 4 x 32 cols
    const int rowBase = blockIdx.y * 128;
    const int colBase = blockIdx.x * 128;

    const float* Ab = A + (size_t)rowBase * K;
    const size_t bOff = (size_t)colBase * K;

    // B loads: 512 16B chunks per tile, 1 per thread (hi and lo each)
    const int bldr = tid >> 2, bldc = (tid & 3) * 8;

    const int q = lane >> 3, r = lane & 7;
    const int a_row = warp_m * 32 + ((q & 1) * 8) + r;
    const int a_kof = (q >> 1) * 8;
    const int b_row = warp_n * 32 + ((q >> 1) * 8) + r;
    const int b_kof = (q & 1) * 8;

    float acc[2][4][4];
#pragma unroll
    for (int i = 0; i < 2; i++)
#pragma unroll
        for (int j = 0; j < 4; j++)
#pragma unroll
            for (int t = 0; t < 4; t++) acc[i][j][t] = 0.f;

    const int NC = K >> 5;

    // A: tile = 1024 float4 chunks, 2 per thread
    float4 areg[2];
    auto ldg_A = [&](int c) {
        const int k0 = c << 5;
#pragma unroll
        for (int i = 0; i < 2; i++) {
            int ch = tid + i * 512;
            int row = ch >> 3, kc = (ch & 7) * 4;
            areg[i] = *(const float4*)(Ab + (size_t)row * K + k0 + kc);
        }
    };
    auto sts_A = [&](int c) {
        const uint32_t st = (c & 1) * STAGE_BYTES;
#pragma unroll
        for (int i = 0; i < 2; i++) {
            int ch = tid + i * 512;
            int row = ch >> 3, kc = (ch & 7) * 4;
            __nv_bfloat16 h[4], l[4];
            split_bf16(areg[i].x, h[0], l[0]);
            split_bf16(areg[i].y, h[1], l[1]);
            split_bf16(areg[i].z, h[2], l[2]);
            split_bf16(areg[i].w, h[3], l[3]);
            uint32_t off = (row * LDT + kc) * 2;
            *(uint2*)(gsm + st + off) = *(uint2*)h;
            *(uint2*)(gsm + st + TILE_BYTES + off) = *(uint2*)l;
        }
    };
    auto load_B = [&](int c) {
        const int k0 = c << 5;
        const uint32_t st = sa + (c & 1) * STAGE_BYTES;
        const uint32_t o0 = (bldr * LDT + bldc) * 2;
        const size_t g0 = (size_t)bldr * K + k0 + bldc;
        cp_async16(st + 2 * TILE_BYTES + o0, Bhi + bOff + g0);
        cp_async16(st + 3 * TILE_BYTES + o0, Blo + bOff + g0);
        CP_COMMIT();
    };

    ldg_A(0);
    load_B(0);
    sts_A(0);

    for (int c = 0; c < NC; c++) {
        if (c + 1 < NC) {
            ldg_A(c + 1);
            load_B(c + 1);
            asm volatile("cp.async.wait_group 1;" ::: "memory");
        } else {
            asm volatile("cp.async.wait_group 0;" ::: "memory");
        }
        __syncthreads();

        const uint32_t st = sa + (c & 1) * STAGE_BYTES;
#pragma unroll
        for (int ks = 0; ks < 2; ks++) {
            uint32_t afh[2][4], afl[2][4];
#pragma unroll
            for (int i = 0; i < 2; i++) {
                uint32_t ao = ((a_row + i * 16) * LDT + ks * 16 + a_kof) * 2;
                ldm_x4(afh[i], st + ao);
                ldm_x4(afl[i], st + TILE_BYTES + ao);
            }
            uint32_t bfh[2][4], bfl[2][4];
#pragma unroll
            for (int ng = 0; ng < 2; ng++) {
                uint32_t bo = ((b_row + ng * 16) * LDT + ks * 16 + b_kof) * 2;
                ldm_x4(bfh[ng], st + 2 * TILE_BYTES + bo);
                ldm_x4(bfl[ng], st + 3 * TILE_BYTES + bo);
            }
#pragma unroll
            for (int i = 0; i < 2; i++)
#pragma unroll
                for (int j = 0; j < 4; j++) {
                    const int g = j >> 1, h = (j & 1) * 2;
                    mma16816(acc[i][j], afh[i], bfh[g][h], bfh[g][h + 1]);
                    mma16816(acc[i][j], afh[i], bfl[g][h], bfl[g][h + 1]);
                    mma16816(acc[i][j], afl[i], bfh[g][h], bfh[g][h + 1]);
                }
        }
        if (c + 1 < NC) sts_A(c + 1);
    }

    const int er = lane >> 2, ec = (lane & 3) * 2;
#pragma unroll
    for (int i = 0; i < 2; i++) {
#pragma unroll
        for (int j = 0; j < 4; j++) {
            int row0 = rowBase + warp_m * 32 + i * 16 + er;
            int col = colBase + warp_n * 32 + j * 8 + ec;
            if (OUT_SPLIT) {
                __nv_bfloat16 h0, l0, h1, l1;
                __nv_bfloat162 ph, pl;
                split_bf16(acc[i][j][0] * 0.125f, h0, l0);
                split_bf16(acc[i][j][1] * 0.125f, h1, l1);
                ph.x = h0; ph.y = h1; pl.x = l0; pl.y = l1;
                *(__nv_bfloat162*)(Chi + (size_t)row0 * N + col) = ph;
                *(__nv_bfloat162*)(Clo + (size_t)row0 * N + col) = pl;
                split_bf16(acc[i][j][2] * 0.125f, h0, l0);
                split_bf16(acc[i][j][3] * 0.125f, h1, l1);
                ph.x = h0; ph.y = h1; pl.x = l0; pl.y = l1;
                *(__nv_bfloat162*)(Chi + (size_t)(row0 + 8) * N + col) = ph;
                *(__nv_bfloat162*)(Clo + (size_t)(row0 + 8) * N + col) = pl;
            } else {
                float2 v0 = make_float2(acc[i][j][0], acc[i][j][1]);
                float2 v1 = make_float2(acc[i][j][2], acc[i][j][3]);
                if (HAS_BIAS) {
                    float2 bv = *(const float2*)(bias + col);
                    v0.x += bv.x; v0.y += bv.y;
                    v1.x += bv.x; v1.y += bv.y;
                }
                *(float2*)(C + (size_t)row0 * N + col) = v0;
                *(float2*)(C + (size_t)(row0 + 8) * N + col) = v1;
            }
        }
    }
}

// ---------------------------------------------------------------------------
// fp32 SGEMM 64x64, dual-B. First half: K -> split hi/lo bf16.
// Second half: V -> transposed split hi/lo bf16 [n][h][s][c pad 80].
// ---------------------------------------------------------------------------
__global__ __launch_bounds__(256) void sgemm64_dual(
    const float* __restrict__ A,
    const float* __restrict__ B1, const float* __restrict__ B2,
    __nv_bfloat16* __restrict__ Khi, __nv_bfloat16* __restrict__ Klo,
    __nv_bfloat16* __restrict__ VThi, __nv_bfloat16* __restrict__ VTlo,
    int M, int N, int K)
{
    __shared__ float As[16][68];
    __shared__ float Bs[16][68];
    const int nb = N >> 6;
    const bool second = (int)blockIdx.x >= nb;
    const float* B = second ? B2 : B1;
    const int tid = threadIdx.x;
    const int rowBase = blockIdx.y * 64;
    const int colBase = (second ? blockIdx.x - nb : blockIdx.x) * 64;
    const int aRow = tid >> 2, aCol = (tid & 3) * 4;
    const int bRow = tid >> 4, bCol = (tid & 15) * 4;
    const int ty = tid >> 4, tx = tid & 15;

    float acc[4][4];
#pragma unroll
    for (int i = 0; i < 4; i++)
#pragma unroll
        for (int j = 0; j < 4; j++) acc[i][j] = 0.f;

    const bool aValid = (rowBase + aRow) < M;
    const float* Aptr = A + (size_t)(rowBase + aRow) * K + aCol;
    const float* Bptr = B + (size_t)bRow * N + colBase + bCol;

    for (int k0 = 0; k0 < K; k0 += 16) {
        float4 av = aValid ? *(const float4*)(Aptr + k0) : make_float4(0, 0, 0, 0);
        float4 bv = *(const float4*)(Bptr + (size_t)k0 * N);
        As[aCol + 0][aRow] = av.x; As[aCol + 1][aRow] = av.y;
        As[aCol + 2][aRow] = av.z; As[aCol + 3][aRow] = av.w;
        *(float4*)&Bs[bRow][bCol] = bv;
        __syncthreads();
#pragma unroll
        for (int kk = 0; kk < 16; kk++) {
            float a[4], b[4];
#pragma unroll
            for (int i = 0; i < 4; i++) a[i] = As[kk][ty * 4 + i];
#pragma unroll
            for (int j = 0; j < 4; j++) b[j] = Bs[kk][tx * 4 + j];
#pragma unroll
            for (int i = 0; i < 4; i++)
#pragma unroll
                for (int j = 0; j < 4; j++) acc[i][j] = fmaf(a[i], b[j], acc[i][j]);
        }
        __syncthreads();
    }
#pragma unroll
    for (int i = 0; i < 4; i++) {
        int rr = rowBase + ty * 4 + i;
        if (rr >= M) continue;
        if (second) {
            int nIdx = rr / GC, cc = rr - nIdx * GC;
#pragma unroll
            for (int j = 0; j < 4; j++) {
                int s = colBase + tx * 4 + j;
                int hh = s >> 6, ss = s & 63;
                size_t o = (((size_t)(nIdx * GH + hh) * 64) + ss) * 80 + cc;
                __nv_bfloat16 h, l;
                split_bf16(acc[i][j], h, l);
                VThi[o] = h;
                VTlo[o] = l;
            }
        } else {
            __nv_bfloat16 h[4], l[4];
#pragma unroll
            for (int j = 0; j < 4; j++) split_bf16(acc[i][j], h[j], l[j]);
            __nv_bfloat162 p;
            size_t o = (size_t)rr * N + colBase + tx * 4;
            p.x = h[0]; p.y = h[1]; *(__nv_bfloat162*)(Khi + o) = p;
            p.x = h[2]; p.y = h[3]; *(__nv_bfloat162*)(Khi + o + 2) = p;
            p.x = l[0]; p.y = l[1]; *(__nv_bfloat162*)(Klo + o) = p;
            p.x = l[2]; p.y = l[3]; *(__nv_bfloat162*)(Klo + o + 2) = p;
        }
    }
}

// Zero the V^T pad columns c in [77,80) for all (n,h,s).
__global__ void zero_vt_pad(__nv_bfloat16* a, __nv_bfloat16* b)
{
    int i = blockIdx.x * blockDim.x + threadIdx.x;
    if (i >= GN * GH * 64 * 3) return;
    int c = 77 + (i % 3);
    int row = i / 3;
    a[(size_t)row * 80 + c] = __float2bfloat16(0.f);
    b[(size_t)row * 80 + c] = __float2bfloat16(0.f);
}

// ---------------------------------------------------------------------------
// TC attention (R13, unchanged): TC scores + TC AV (bf16x3), fp32 softmax.
// ---------------------------------------------------------------------------
#define QP 88
#define LDKK 72
#define VTP 88
#define H_QHI 0
#define H_QLO 11264
#define H_KHI 22528
#define H_KLO 36352
#define H_VTHI 50176
#define H_VTLO 61440
#define H_WS 72704
#define H_SMEM (H_WS + 64 * 80 * 4)   // 93184

__global__ __launch_bounds__(256) void attn_tc(
    const __nv_bfloat16* __restrict__ qhi, const __nv_bfloat16* __restrict__ qlo,
    const __nv_bfloat16* __restrict__ khi, const __nv_bfloat16* __restrict__ klo,
    const __nv_bfloat16* __restrict__ vthi, const __nv_bfloat16* __restrict__ vtlo,
    float* __restrict__ og)
{
    extern __shared__ __align__(16) char smb[];
    const uint32_t sb = smem_u32(smb);
    float* ws = (float*)(smb + H_WS);   // [64][80]

    const int n = blockIdx.z, h = blockIdx.y;
    const int qbase = blockIdx.x * 64;
    const int tid = threadIdx.x;
    const int wid = tid >> 5, lane = tid & 31;

    const size_t kOff = (size_t)n * GC * GD + h * GS;
    const size_t qOff = ((size_t)n * GQ + qbase) * GD + h * GS;
    const size_t vtOff = ((size_t)(n * GH + h) * 64) * 80;

    for (int i = tid; i < 19 * 32; i += 256) {
        int rr = 77 + (i >> 5), cc = (i & 31) * 2;
        *(uint32_t*)(smb + H_KHI + (rr * LDKK + cc) * 2) = 0;
        *(uint32_t*)(smb + H_KLO + (rr * LDKK + cc) * 2) = 0;
    }
    for (int i = tid; i < GC * 8; i += 256) {
        int c = i >> 3, ck = (i & 7) * 8;
        cp_async16(sb + H_KHI + (c * LDKK + ck) * 2, khi + kOff + (size_t)c * GD + ck);
        cp_async16(sb + H_KLO + (c * LDKK + ck) * 2, klo + kOff + (size_t)c * GD + ck);
    }
    for (int i = tid; i < 64 * 8; i += 256) {
        int rr = i >> 3, ck = (i & 7) * 8;
        cp_async16(sb + H_QHI + (rr * QP + ck) * 2, qhi + qOff + (size_t)rr * GD + ck);
        cp_async16(sb + H_QLO + (rr * QP + ck) * 2, qlo + qOff + (size_t)rr * GD + ck);
    }
    for (int i = tid; i < 64 * 10; i += 256) {
        int s = i / 10, ck = (i % 10) * 8;
        cp_async16(sb + H_VTHI + (s * VTP + ck) * 2, vthi + vtOff + (size_t)s * 80 + ck);
        cp_async16(sb + H_VTLO + (s * VTP + ck) * 2, vtlo + vtOff + (size_t)s * 80 + ck);
    }
    CP_COMMIT();
    asm volatile("cp.async.wait_group 0;" ::: "memory");
    __syncthreads();

    const int q = lane >> 3, rr = lane & 7;
    const int warp_m = wid & 3, warp_n = wid >> 2;
    const int a_r = warp_m * 16 + (q & 1) * 8 + rr;
    const int a_k = (q >> 1) * 8;
    const int b_k = (q & 1) * 8;
    const int er = lane >> 2, ec = (lane & 3) * 2;

    // ---- phase 1: TC scores
    {
        const int b_rbase = warp_n * 48 + (q >> 1) * 8 + rr;
        float sc[6][4];
#pragma unroll
        for (int j = 0; j < 6; j++)
#pragma unroll
            for (int t = 0; t < 4; t++) sc[j][t] = 0.f;

#pragma unroll
        for (int kk = 0; kk < 4; kk++) {
            int kof = kk * 16;
            uint32_t afh[4], afl[4];
            ldm_x4(afh, sb + H_QHI + (a_r * QP + kof + a_k) * 2);
            ldm_x4(afl, sb + H_QLO + (a_r * QP + kof + a_k) * 2);
            uint32_t bfh[3][4], bfl[3][4];
#pragma unroll
            for (int ng = 0; ng < 3; ng++) {
                uint32_t bo = ((b_rbase + ng * 16) * LDKK + kof + b_k) * 2;
                ldm_x4(bfh[ng], sb + H_KHI + bo);
                ldm_x4(bfl[ng], sb + H_KLO + bo);
            }
#pragma unroll
            for (int j = 0; j < 6; j++) {
                const int g = j >> 1, hs = (j & 1) * 2;
                mma16816(sc[j], afh, bfh[g][hs], bfh[g][hs + 1]);
                mma16816(sc[j], afh, bfl[g][hs], bfl[g][hs + 1]);
                mma16816(sc[j], afl, bfh[g][hs], bfh[g][hs + 1]);
            }
        }
#pragma unroll
        for (int j = 0; j < 6; j++) {
            int col = warp_n * 48 + j * 8 + ec;
            if (col < 80) {
                int row = warp_m * 16 + er;
                ws[row * 80 + col] = sc[j][0];
                ws[row * 80 + col + 1] = sc[j][1];
                ws[(row + 8) * 80 + col] = sc[j][2];
                ws[(row + 8) * 80 + col + 1] = sc[j][3];
            }
        }
    }
    __syncthreads();

    // ---- phase 2: softmax -> hi/lo weights into reused Q buffers
    {
        const int r0 = wid * 8;
        const bool c2ok = (lane < GC - 64);
#pragma unroll
        for (int r = 0; r < 8; r++) {
            int row = r0 + r;
            float s0 = ws[row * 80 + lane];
            float s1 = ws[row * 80 + lane + 32];
            float s2 = c2ok ? ws[row * 80 + lane + 64] : -1e30f;
            float m = fmaxf(fmaxf(s0, s1), s2);
#pragma unroll
            for (int o = 16; o; o >>= 1) m = fmaxf(m, __shfl_xor_sync(0xffffffffu, m, o));
            float e0 = __expf(s0 - m);
            float e1 = __expf(s1 - m);
            float e2 = c2ok ? __expf(s2 - m) : 0.f;
            float sum = e0 + e1 + e2;
#pragma unroll
            for (int o = 16; o; o >>= 1) sum += __shfl_xor_sync(0xffffffffu, sum, o);
            float inv = __frcp_rn(sum);
            __nv_bfloat16 hh, ll;
            split_bf16(e0 * inv, hh, ll);
            *(__nv_bfloat16*)(smb + H_QHI + (row * QP + lane) * 2) = hh;
            *(__nv_bfloat16*)(smb + H_QLO + (row * QP + lane) * 2) = ll;
            split_bf16(e1 * inv, hh, ll);
            *(__nv_bfloat16*)(smb + H_QHI + (row * QP + lane + 32) * 2) = hh;
            *(__nv_bfloat16*)(smb + H_QLO + (row * QP + lane + 32) * 2) = ll;
            if (c2ok) {
                split_bf16(e2 * inv, hh, ll);
                *(__nv_bfloat16*)(smb + H_QHI + (row * QP + lane + 64) * 2) = hh;
                *(__nv_bfloat16*)(smb + H_QLO + (row * QP + lane + 64) * 2) = ll;
            } else if (lane + 64 < 80) {
                *(__nv_bfloat16*)(smb + H_QHI + (row * QP + lane + 64) * 2) = __float2bfloat16(0.f);
                *(__nv_bfloat16*)(smb + H_QLO + (row * QP + lane + 64) * 2) = __float2bfloat16(0.f);
            }
        }
    }
    __syncthreads();

    // ---- phase 3: TC AV
    {
        const int b_rbase = warp_n * 32 + (q >> 1) * 8 + rr;
        float av[4][4];
#pragma unroll
        for (int j = 0; j < 4; j++)
#pragma unroll
            for (int t = 0; t < 4; t++) av[j][t] = 0.f;

#pragma unroll
        for (int kk = 0; kk < 5; kk++) {
            int kof = kk * 16;
            uint32_t afh[4], afl[4];
            ldm_x4(afh, sb + H_QHI + (a_r * QP + kof + a_k) * 2);
            ldm_x4(afl, sb + H_QLO + (a_r * QP + kof + a_k) * 2);
            uint32_t bfh[2][4], bfl[2][4];
#pragma unroll
            for (int ng = 0; ng < 2; ng++) {
                uint32_t bo = ((b_rbase + ng * 16) * VTP + kof + b_k) * 2;
                ldm_x4(bfh[ng], sb + H_VTHI + bo);
                ldm_x4(bfl[ng], sb + H_VTLO + bo);
            }
#pragma unroll
            for (int j = 0; j < 4; j++) {
                const int g = j >> 1, hs = (j & 1) * 2;
                mma16816(av[j], afh, bfh[g][hs], bfh[g][hs + 1]);
                mma16816(av[j], afh, bfl[g][hs], bfl[g][hs + 1]);
                mma16816(av[j], afl, bfh[g][hs], bfh[g][hs + 1]);
            }
        }

        float* ob = og + ((size_t)n * GQ + qbase) * GD + h * GS;
#pragma unroll
        for (int j = 0; j < 4; j++) {
            int col = warp_n * 32 + j * 8 + ec;
            int row = warp_m * 16 + er;
            *(float2*)(ob + (size_t)row * GD + col) = make_float2(av[j][0], av[j][1]);
            *(float2*)(ob + (size_t)(row + 8) * GD + col) = make_float2(av[j][2], av[j][3]);
        }
    }
}

// ---------------------------------------------------------------------------
// W[K][N] fp32 -> Wt[N][K] hi/lo bf16
__global__ void transpose_split(const float* __restrict__ W,
                                __nv_bfloat16* __restrict__ Whi,
                                __nv_bfloat16* __restrict__ Wlo, int K, int N)
{
    __shared__ float t[32][33];
    int k0 = blockIdx.y * 32, n0 = blockIdx.x * 32;
    int x = threadIdx.x, y = threadIdx.y;  // 32 x 8
#pragma unroll
    for (int i = 0; i < 32; i += 8) t[y + i][x] = W[(size_t)(k0 + y + i) * N + n0 + x];
    __syncthreads();
#pragma unroll
    for (int i = 0; i < 32; i += 8) {
        __nv_bfloat16 h, l;
        split_bf16(t[x][y + i], h, l);
        Whi[(size_t)(n0 + y + i) * K + k0 + x] = h;
        Wlo[(size_t)(n0 + y + i) * K + k0 + x] = l;
    }
}

// ---------------------------------------------------------------------------
extern "C" void kernel_launch(void* const* d_in, const int* in_sizes, int n_in,
                              void* d_out, int out_size)
{
    const float* query   = (const float*)d_in[0];
    const float* context = (const float*)d_in[1];
    const float* Wq      = (const float*)d_in[2];
    const float* Wk      = (const float*)d_in[3];
    const float* Wv      = (const float*)d_in[4];
    const float* Wo      = (const float*)d_in[5];
    const float* bo      = (const float*)d_in[6];
    float* out = (float*)d_out;

    void *pa, *pqh, *pql, *pkh, *pkl, *pvth, *pvtl, *pwqh, *pwql, *pwoh, *pwol;
    cudaGetSymbolAddress(&pa, g_att);
    cudaGetSymbolAddress(&pqh, g_qhi);
    cudaGetSymbolAddress(&pql, g_qlo);
    cudaGetSymbolAddress(&pkh, g_khi);
    cudaGetSymbolAddress(&pkl, g_klo);
    cudaGetSymbolAddress(&pvth, g_vThi);
    cudaGetSymbolAddress(&pvtl, g_vTlo);
    cudaGetSymbolAddress(&pwqh, g_wqT_hi);
    cudaGetSymbolAddress(&pwql, g_wqT_lo);
    cudaGetSymbolAddress(&pwoh, g_woT_hi);
    cudaGetSymbolAddress(&pwol, g_woT_lo);

    cudaFuncSetAttribute((const void*)gemm_mma3f<false, true>,
                         cudaFuncAttributeMaxDynamicSharedMemorySize, GEMM_SMEM);
    cudaFuncSetAttribute((const void*)gemm_mma3f<true, false>,
                         cudaFuncAttributeMaxDynamicSharedMemorySize, GEMM_SMEM);
    cudaFuncSetAttribute((const void*)attn_tc,
                         cudaFuncAttributeMaxDynamicSharedMemorySize, H_SMEM);

    // prep
    {
        dim3 b(32, 8);
        transpose_split<<<dim3(GD / 32, GD / 32), b>>>(Wq, (__nv_bfloat16*)pwqh,
                                                       (__nv_bfloat16*)pwql, GD, GD);
        transpose_split<<<dim3(GD / 32, GD / 32), b>>>(Wo, (__nv_bfloat16*)pwoh,
                                                       (__nv_bfloat16*)pwol, GD, GD);
        zero_vt_pad<<<(GN * GH * 64 * 3 + 255) / 256, 256>>>(
            (__nv_bfloat16*)pvth, (__nv_bfloat16*)pvtl);
    }
    // K (split) + V (transposed split) projections fused
    {
        dim3 grid((GD / 64) * 2, (GN * GC + 63) / 64);
        sgemm64_dual<<<grid, 256>>>(context, Wk, Wv,
                                    (__nv_bfloat16*)pkh, (__nv_bfloat16*)pkl,
                                    (__nv_bfloat16*)pvth, (__nv_bfloat16*)pvtl,
                                    GN * GC, GD, GDC);
    }
    // Q projection: 512-thread gemm, split+scaled epilogue
    {
        dim3 grid(GD / 128, GM / 128);
        gemm_mma3f<false, true><<<grid, 512, GEMM_SMEM>>>(
            query, (const __nv_bfloat16*)pwqh, (const __nv_bfloat16*)pwql,
            nullptr, nullptr, (__nv_bfloat16*)pqh, (__nv_bfloat16*)pql,
            GM, GD, GD);
    }
    // attention: full TC
    {
        dim3 grid(GQ / 64, GH, GN);
        attn_tc<<<grid, 256, H_SMEM>>>(
            (const __nv_bfloat16*)pqh, (const __nv_bfloat16*)pql,
            (const __nv_bfloat16*)pkh, (const __nv_bfloat16*)pkl,
            (const __nv_bfloat16*)pvth, (const __nv_bfloat16*)pvtl,
            (float*)pa);
    }
    // O projection + bias: 512-thread gemm, fp32 epilogue
    {
        dim3 grid(GD / 128, GM / 128);
        gemm_mma3f<true, false><<<grid, 512, GEMM_SMEM>>>(
            (const float*)pa, (const __nv_bfloat16*)pwoh, (const __nv_bfloat16*)pwol,
            bo, out, nullptr, nullptr, GM, GD, GD);
    }
}

// round 15
// speedup vs baseline: 1.0106x; 1.0106x over previous
#include <cuda_runtime.h>
#include <cuda_bf16.h>
#include <cstdint>

#define GN 16
#define GQ 4096
#define GC 77
#define GD 512
#define GDC 768
#define GH 8
#define GS 64
#define GM (GN * GQ)  // 65536

// ---------------- scratch (device globals, allocation-free) ----------------
__device__ __nv_bfloat16 g_atthi[(size_t)GM * GD];       // attn out pre-split
__device__ __nv_bfloat16 g_attlo[(size_t)GM * GD];
__device__ __nv_bfloat16 g_qhi[(size_t)GM * GD];         // q pre-split (scaled)
__device__ __nv_bfloat16 g_qlo[(size_t)GM * GD];
__device__ __nv_bfloat16 g_khi[(size_t)GN * GC * GD];    // k pre-split
__device__ __nv_bfloat16 g_klo[(size_t)GN * GC * GD];
__device__ __nv_bfloat16 g_vThi[(size_t)GN * GH * 64 * 80];  // V^T pre-split, c pad 80
__device__ __nv_bfloat16 g_vTlo[(size_t)GN * GH * 64 * 80];
__device__ __nv_bfloat16 g_wqT_hi[GD * GD], g_wqT_lo[GD * GD];
__device__ __nv_bfloat16 g_woT_hi[GD * GD], g_woT_lo[GD * GD];

__device__ __forceinline__ uint32_t smem_u32(const void* p) {
    uint32_t a;
    asm("{ .reg .u64 t; cvta.to.shared.u64 t, %1; cvt.u32.u64 %0, t; }"
        : "=r"(a) : "l"(p));
    return a;
}
__device__ __forceinline__ void cp_async16(uint32_t dst, const void* src) {
    asm volatile("cp.async.cg.shared.global [%0], [%1], 16;"
                 :: "r"(dst), "l"(src) : "memory");
}
#define CP_COMMIT() asm volatile("cp.async.commit_group;" ::: "memory")

__device__ __forceinline__ void ldm_x4(uint32_t (&f)[4], uint32_t addr) {
    asm volatile("ldmatrix.sync.aligned.m8n8.x4.shared.b16 {%0,%1,%2,%3}, [%4];"
                 : "=r"(f[0]), "=r"(f[1]), "=r"(f[2]), "=r"(f[3]) : "r"(addr));
}
__device__ __forceinline__ void mma16816(float (&d)[4], const uint32_t (&a)[4],
                                         uint32_t b0, uint32_t b1) {
    asm volatile(
        "mma.sync.aligned.m16n8k16.row.col.f32.bf16.bf16.f32 "
        "{%0,%1,%2,%3}, {%4,%5,%6,%7}, {%8,%9}, {%0,%1,%2,%3};"
        : "+f"(d[0]), "+f"(d[1]), "+f"(d[2]), "+f"(d[3])
        : "r"(a[0]), "r"(a[1]), "r"(a[2]), "r"(a[3]), "r"(b0), "r"(b1));
}

__device__ __forceinline__ void split_bf16(float x, __nv_bfloat16& hi, __nv_bfloat16& lo) {
    hi = __float2bfloat16_rn(x);
    lo = __float2bfloat16_rn(x - __bfloat162float(hi));
}

// ---------------------------------------------------------------------------
// bf16x3 mma.sync GEMM — R6/R13 GOLDEN 256-thread mainloop (FROZEN term order).
// A_SPLIT=false: fp32 A, in-kernel split (LDG+STS).  A_SPLIT=true: pre-split
// hi/lo bf16 A loaded via cp.async (same machinery as B).
// OUT_SPLIT=false: fp32 C (+bias).  OUT_SPLIT=true: hi/lo bf16 (scaled 0.125).
// BANNED (R7-R9 corruption): regrouped inner loop; launch_bounds minBlocks=2.
// R14: 512-thread/32x32 warp-tile variant was SLOWER (ldmatrix-bound) — banned.
// ---------------------------------------------------------------------------
#define LDT 40
#define TILE_B (128 * LDT)
#define TILE_BYTES (TILE_B * 2)
#define STAGE_BYTES (4 * TILE_BYTES)
#define GEMM_SMEM (2 * STAGE_BYTES)   // 81920 B

template <bool HAS_BIAS, bool OUT_SPLIT, bool A_SPLIT>
__global__ __launch_bounds__(256) void gemm_mma3f(
    const float* __restrict__ A,
    const __nv_bfloat16* __restrict__ Ahi, const __nv_bfloat16* __restrict__ Alo,
    const __nv_bfloat16* __restrict__ Bhi, const __nv_bfloat16* __restrict__ Blo,
    const float* __restrict__ bias, float* __restrict__ C,
    __nv_bfloat16* __restrict__ Chi, __nv_bfloat16* __restrict__ Clo,
    int M, int N, int K)
{
    extern __shared__ __align__(16) char gsm[];
    const uint32_t sa = smem_u32(gsm);

    const int tid = threadIdx.x;
    const int wid = tid >> 5, lane = tid & 31;
    const int warp_m = wid & 3;
    const int warp_n = wid >> 2;
    const int rowBase = blockIdx.y * 128;
    const int colBase = blockIdx.x * 128;

    const float* Ab = A_SPLIT ? nullptr : (A + (size_t)rowBase * K);
    const size_t aOff = (size_t)rowBase * K;
    const size_t bOff = (size_t)colBase * K;

    const int ldr0 = tid >> 2, ldc0 = (tid & 3);
    const int ldr1 = (tid + 256) >> 2, ldc1 = (tid & 3);

    const int q = lane >> 3, r = lane & 7;
    const int a_row = warp_m * 32 + ((q & 1) * 8) + r;
    const int a_kof = (q >> 1) * 8;
    const int b_row = warp_n * 64 + ((q >> 1) * 8) + r;
    const int b_kof = (q & 1) * 8;

    float acc[2][8][4];
#pragma unroll
    for (int i = 0; i < 2; i++)
#pragma unroll
        for (int j = 0; j < 8; j++)
#pragma unroll
            for (int t = 0; t < 4; t++) acc[i][j][t] = 0.f;

    const int NC = K >> 5;

    float4 areg[4];
    auto ldg_A = [&](int c) {
        const int k0 = c << 5;
#pragma unroll
        for (int i = 0; i < 4; i++) {
            int ch = tid + i * 256;
            int row = ch >> 3, kc = (ch & 7) * 4;
            areg[i] = *(const float4*)(Ab + (size_t)row * K + k0 + kc);
        }
    };
    auto sts_A = [&](int c) {
        const uint32_t st = (c & 1) * STAGE_BYTES;
#pragma unroll
        for (int i = 0; i < 4; i++) {
            int ch = tid + i * 256;
            int row = ch >> 3, kc = (ch & 7) * 4;
            __nv_bfloat16 h[4], l[4];
            split_bf16(areg[i].x, h[0], l[0]);
            split_bf16(areg[i].y, h[1], l[1]);
            split_bf16(areg[i].z, h[2], l[2]);
            split_bf16(areg[i].w, h[3], l[3]);
            uint32_t off = (row * LDT + kc) * 2;
            *(uint2*)(gsm + st + off) = *(uint2*)h;
            *(uint2*)(gsm + st + TILE_BYTES + off) = *(uint2*)l;
        }
    };
    auto load_AB = [&](int c) {   // cp.async: B always; A too when A_SPLIT
        const int k0 = c << 5;
        const uint32_t st = sa + (c & 1) * STAGE_BYTES;
        const uint32_t o0 = (ldr0 * LDT + ldc0 * 8) * 2;
        const uint32_t o1 = (ldr1 * LDT + ldc1 * 8) * 2;
        const size_t g0 = (size_t)ldr0 * K + k0 + ldc0 * 8;
        const size_t g1 = (size_t)ldr1 * K + k0 + ldc1 * 8;
        if (A_SPLIT) {
            cp_async16(st + o0, Ahi + aOff + g0);
            cp_async16(st + o1, Ahi + aOff + g1);
            cp_async16(st + TILE_BYTES + o0, Alo + aOff + g0);
            cp_async16(st + TILE_BYTES + o1, Alo + aOff + g1);
        }
        cp_async16(st + 2 * TILE_BYTES + o0, Bhi + bOff + g0);
        cp_async16(st + 2 * TILE_BYTES + o1, Bhi + bOff + g1);
        cp_async16(st + 3 * TILE_BYTES + o0, Blo + bOff + g0);
        cp_async16(st + 3 * TILE_BYTES + o1, Blo + bOff + g1);
        CP_COMMIT();
    };

    if (!A_SPLIT) ldg_A(0);
    load_AB(0);
    if (!A_SPLIT) sts_A(0);

    for (int c = 0; c < NC; c++) {
        if (c + 1 < NC) {
            if (!A_SPLIT) ldg_A(c + 1);
            load_AB(c + 1);
            asm volatile("cp.async.wait_group 1;" ::: "memory");
        } else {
            asm volatile("cp.async.wait_group 0;" ::: "memory");
        }
        __syncthreads();

        const uint32_t st = sa + (c & 1) * STAGE_BYTES;
#pragma unroll
        for (int ks = 0; ks < 2; ks++) {
            uint32_t afh[2][4], afl[2][4];
#pragma unroll
            for (int i = 0; i < 2; i++) {
                uint32_t ao = ((a_row + i * 16) * LDT + ks * 16 + a_kof) * 2;
                ldm_x4(afh[i], st + ao);
                ldm_x4(afl[i], st + TILE_BYTES + ao);
            }
            uint32_t bfh[4][4], bfl[4][4];
#pragma unroll
            for (int ng = 0; ng < 4; ng++) {
                uint32_t bo = ((b_row + ng * 16) * LDT + ks * 16 + b_kof) * 2;
                ldm_x4(bfh[ng], st + 2 * TILE_BYTES + bo);
                ldm_x4(bfl[ng], st + 3 * TILE_BYTES + bo);
            }
#pragma unroll
            for (int i = 0; i < 2; i++)
#pragma unroll
                for (int j = 0; j < 8; j++) {
                    const int g = j >> 1, h = (j & 1) * 2;
                    mma16816(acc[i][j], afh[i], bfh[g][h], bfh[g][h + 1]);
                    mma16816(acc[i][j], afh[i], bfl[g][h], bfl[g][h + 1]);
                    mma16816(acc[i][j], afl[i], bfh[g][h], bfh[g][h + 1]);
                }
        }
        if (!A_SPLIT && c + 1 < NC) sts_A(c + 1);
    }

    const int er = lane >> 2, ec = (lane & 3) * 2;
#pragma unroll
    for (int i = 0; i < 2; i++) {
#pragma unroll
        for (int j = 0; j < 8; j++) {
            int row0 = rowBase + warp_m * 32 + i * 16 + er;
            int col = colBase + warp_n * 64 + j * 8 + ec;
            if (OUT_SPLIT) {
                __nv_bfloat16 h0, l0, h1, l1;
                __nv_bfloat162 ph, pl;
                split_bf16(acc[i][j][0] * 0.125f, h0, l0);
                split_bf16(acc[i][j][1] * 0.125f, h1, l1);
                ph.x = h0; ph.y = h1; pl.x = l0; pl.y = l1;
                *(__nv_bfloat162*)(Chi + (size_t)row0 * N + col) = ph;
                *(__nv_bfloat162*)(Clo + (size_t)row0 * N + col) = pl;
                split_bf16(acc[i][j][2] * 0.125f, h0, l0);
                split_bf16(acc[i][j][3] * 0.125f, h1, l1);
                ph.x = h0; ph.y = h1; pl.x = l0; pl.y = l1;
                *(__nv_bfloat162*)(Chi + (size_t)(row0 + 8) * N + col) = ph;
                *(__nv_bfloat162*)(Clo + (size_t)(row0 + 8) * N + col) = pl;
            } else {
                float2 v0 = make_float2(acc[i][j][0], acc[i][j][1]);
                float2 v1 = make_float2(acc[i][j][2], acc[i][j][3]);
                if (HAS_BIAS) {
                    float2 bv = *(const float2*)(bias + col);
                    v0.x += bv.x; v0.y += bv.y;
                    v1.x += bv.x; v1.y += bv.y;
                }
                *(float2*)(C + (size_t)row0 * N + col) = v0;
                *(float2*)(C + (size_t)(row0 + 8) * N + col) = v1;
            }
        }
    }
}

// ---------------------------------------------------------------------------
// fp32 SGEMM 64x64, dual-B. First half: K -> split hi/lo bf16.
// Second half: V -> transposed split hi/lo bf16 [n][h][s][c pad 80].
// ---------------------------------------------------------------------------
__global__ __launch_bounds__(256) void sgemm64_dual(
    const float* __restrict__ A,
    const float* __restrict__ B1, const float* __restrict__ B2,
    __nv_bfloat16* __restrict__ Khi, __nv_bfloat16* __restrict__ Klo,
    __nv_bfloat16* __restrict__ VThi, __nv_bfloat16* __restrict__ VTlo,
    int M, int N, int K)
{
    __shared__ float As[16][68];
    __shared__ float Bs[16][68];
    const int nb = N >> 6;
    const bool second = (int)blockIdx.x >= nb;
    const float* B = second ? B2 : B1;
    const int tid = threadIdx.x;
    const int rowBase = blockIdx.y * 64;
    const int colBase = (second ? blockIdx.x - nb : blockIdx.x) * 64;
    const int aRow = tid >> 2, aCol = (tid & 3) * 4;
    const int bRow = tid >> 4, bCol = (tid & 15) * 4;
    const int ty = tid >> 4, tx = tid & 15;

    float acc[4][4];
#pragma unroll
    for (int i = 0; i < 4; i++)
#pragma unroll
        for (int j = 0; j < 4; j++) acc[i][j] = 0.f;

    const bool aValid = (rowBase + aRow) < M;
    const float* Aptr = A + (size_t)(rowBase + aRow) * K + aCol;
    const float* Bptr = B + (size_t)bRow * N + colBase + bCol;

    for (int k0 = 0; k0 < K; k0 += 16) {
        float4 av = aValid ? *(const float4*)(Aptr + k0) : make_float4(0, 0, 0, 0);
        float4 bv = *(const float4*)(Bptr + (size_t)k0 * N);
        As[aCol + 0][aRow] = av.x; As[aCol + 1][aRow] = av.y;
        As[aCol + 2][aRow] = av.z; As[aCol + 3][aRow] = av.w;
        *(float4*)&Bs[bRow][bCol] = bv;
        __syncthreads();
#pragma unroll
        for (int kk = 0; kk < 16; kk++) {
            float a[4], b[4];
#pragma unroll
            for (int i = 0; i < 4; i++) a[i] = As[kk][ty * 4 + i];
#pragma unroll
            for (int j = 0; j < 4; j++) b[j] = Bs[kk][tx * 4 + j];
#pragma unroll
            for (int i = 0; i < 4; i++)
#pragma unroll
                for (int j = 0; j < 4; j++) acc[i][j] = fmaf(a[i], b[j], acc[i][j]);
        }
        __syncthreads();
    }
#pragma unroll
    for (int i = 0; i < 4; i++) {
        int rr = rowBase + ty * 4 + i;
        if (rr >= M) continue;
        if (second) {
            int nIdx = rr / GC, cc = rr - nIdx * GC;
#pragma unroll
            for (int j = 0; j < 4; j++) {
                int s = colBase + tx * 4 + j;
                int hh = s >> 6, ss = s & 63;
                size_t o = (((size_t)(nIdx * GH + hh) * 64) + ss) * 80 + cc;
                __nv_bfloat16 h, l;
                split_bf16(acc[i][j], h, l);
                VThi[o] = h;
                VTlo[o] = l;
            }
        } else {
            __nv_bfloat16 h[4], l[4];
#pragma unroll
            for (int j = 0; j < 4; j++) split_bf16(acc[i][j], h[j], l[j]);
            __nv_bfloat162 p;
            size_t o = (size_t)rr * N + colBase + tx * 4;
            p.x = h[0]; p.y = h[1]; *(__nv_bfloat162*)(Khi + o) = p;
            p.x = h[2]; p.y = h[3]; *(__nv_bfloat162*)(Khi + o + 2) = p;
            p.x = l[0]; p.y = l[1]; *(__nv_bfloat162*)(Klo + o) = p;
            p.x = l[2]; p.y = l[3]; *(__nv_bfloat162*)(Klo + o + 2) = p;
        }
    }
}

// Zero the V^T pad columns c in [77,80) for all (n,h,s).
__global__ void zero_vt_pad(__nv_bfloat16* a, __nv_bfloat16* b)
{
    int i = blockIdx.x * blockDim.x + threadIdx.x;
    if (i >= GN * GH * 64 * 3) return;
    int c = 77 + (i % 3);
    int row = i / 3;
    a[(size_t)row * 80 + c] = __float2bfloat16(0.f);
    b[(size_t)row * 80 + c] = __float2bfloat16(0.f);
}

// ---------------------------------------------------------------------------
// TC attention (R13 structure): TC scores + TC AV (bf16x3), fp32 softmax.
// Output now pre-split hi/lo bf16 for the A-presplit O-projection.
// ---------------------------------------------------------------------------
#define QP 88
#define LDKK 72
#define VTP 88
#define H_QHI 0
#define H_QLO 11264
#define H_KHI 22528
#define H_KLO 36352
#define H_VTHI 50176
#define H_VTLO 61440
#define H_WS 72704
#define H_SMEM (H_WS + 64 * 80 * 4)   // 93184

__global__ __launch_bounds__(256) void attn_tc(
    const __nv_bfloat16* __restrict__ qhi, const __nv_bfloat16* __restrict__ qlo,
    const __nv_bfloat16* __restrict__ khi, const __nv_bfloat16* __restrict__ klo,
    const __nv_bfloat16* __restrict__ vthi, const __nv_bfloat16* __restrict__ vtlo,
    __nv_bfloat16* __restrict__ oghi, __nv_bfloat16* __restrict__ oglo)
{
    extern __shared__ __align__(16) char smb[];
    const uint32_t sb = smem_u32(smb);
    float* ws = (float*)(smb + H_WS);   // [64][80]

    const int n = blockIdx.z, h = blockIdx.y;
    const int qbase = blockIdx.x * 64;
    const int tid = threadIdx.x;
    const int wid = tid >> 5, lane = tid & 31;

    const size_t kOff = (size_t)n * GC * GD + h * GS;
    const size_t qOff = ((size_t)n * GQ + qbase) * GD + h * GS;
    const size_t vtOff = ((size_t)(n * GH + h) * 64) * 80;

    for (int i = tid; i < 19 * 32; i += 256) {
        int rr = 77 + (i >> 5), cc = (i & 31) * 2;
        *(uint32_t*)(smb + H_KHI + (rr * LDKK + cc) * 2) = 0;
        *(uint32_t*)(smb + H_KLO + (rr * LDKK + cc) * 2) = 0;
    }
    for (int i = tid; i < GC * 8; i += 256) {
        int c = i >> 3, ck = (i & 7) * 8;
        cp_async16(sb + H_KHI + (c * LDKK + ck) * 2, khi + kOff + (size_t)c * GD + ck);
        cp_async16(sb + H_KLO + (c * LDKK + ck) * 2, klo + kOff + (size_t)c * GD + ck);
    }
    for (int i = tid; i < 64 * 8; i += 256) {
        int rr = i >> 3, ck = (i & 7) * 8;
        cp_async16(sb + H_QHI + (rr * QP + ck) * 2, qhi + qOff + (size_t)rr * GD + ck);
        cp_async16(sb + H_QLO + (rr * QP + ck) * 2, qlo + qOff + (size_t)rr * GD + ck);
    }
    for (int i = tid; i < 64 * 10; i += 256) {
        int s = i / 10, ck = (i % 10) * 8;
        cp_async16(sb + H_VTHI + (s * VTP + ck) * 2, vthi + vtOff + (size_t)s * 80 + ck);
        cp_async16(sb + H_VTLO + (s * VTP + ck) * 2, vtlo + vtOff + (size_t)s * 80 + ck);
    }
    CP_COMMIT();
    asm volatile("cp.async.wait_group 0;" ::: "memory");
    __syncthreads();

    const int q = lane >> 3, rr = lane & 7;
    const int warp_m = wid & 3, warp_n = wid >> 2;
    const int a_r = warp_m * 16 + (q & 1) * 8 + rr;
    const int a_k = (q >> 1) * 8;
    const int b_k = (q & 1) * 8;
    const int er = lane >> 2, ec = (lane & 3) * 2;

    // ---- phase 1: TC scores
    {
        const int b_rbase = warp_n * 48 + (q >> 1) * 8 + rr;
        float sc[6][4];
#pragma unroll
        for (int j = 0; j < 6; j++)
#pragma unroll
            for (int t = 0; t < 4; t++) sc[j][t] = 0.f;

#pragma unroll
        for (int kk = 0; kk < 4; kk++) {
            int kof = kk * 16;
            uint32_t afh[4], afl[4];
            ldm_x4(afh, sb + H_QHI + (a_r * QP + kof + a_k) * 2);
            ldm_x4(afl, sb + H_QLO + (a_r * QP + kof + a_k) * 2);
            uint32_t bfh[3][4], bfl[3][4];
#pragma unroll
            for (int ng = 0; ng < 3; ng++) {
                uint32_t bo = ((b_rbase + ng * 16) * LDKK + kof + b_k) * 2;
                ldm_x4(bfh[ng], sb + H_KHI + bo);
                ldm_x4(bfl[ng], sb + H_KLO + bo);
            }
#pragma unroll
            for (int j = 0; j < 6; j++) {
                const int g = j >> 1, hs = (j & 1) * 2;
                mma16816(sc[j], afh, bfh[g][hs], bfh[g][hs + 1]);
                mma16816(sc[j], afh, bfl[g][hs], bfl[g][hs + 1]);
                mma16816(sc[j], afl, bfh[g][hs], bfh[g][hs + 1]);
            }
        }
#pragma unroll
        for (int j = 0; j < 6; j++) {
            int col = warp_n * 48 + j * 8 + ec;
            if (col < 80) {
                int row = warp_m * 16 + er;
                ws[row * 80 + col] = sc[j][0];
                ws[row * 80 + col + 1] = sc[j][1];
                ws[(row + 8) * 80 + col] = sc[j][2];
                ws[(row + 8) * 80 + col + 1] = sc[j][3];
            }
        }
    }
    __syncthreads();

    // ---- phase 2: softmax -> hi/lo weights into reused Q buffers
    {
        const int r0 = wid * 8;
        const bool c2ok = (lane < GC - 64);
#pragma unroll
        for (int r = 0; r < 8; r++) {
            int row = r0 + r;
            float s0 = ws[row * 80 + lane];
            float s1 = ws[row * 80 + lane + 32];
            float s2 = c2ok ? ws[row * 80 + lane + 64] : -1e30f;
            float m = fmaxf(fmaxf(s0, s1), s2);
#pragma unroll
            for (int o = 16; o; o >>= 1) m = fmaxf(m, __shfl_xor_sync(0xffffffffu, m, o));
            float e0 = __expf(s0 - m);
            float e1 = __expf(s1 - m);
            float e2 = c2ok ? __expf(s2 - m) : 0.f;
            float sum = e0 + e1 + e2;
#pragma unroll
            for (int o = 16; o; o >>= 1) sum += __shfl_xor_sync(0xffffffffu, sum, o);
            float inv = __frcp_rn(sum);
            __nv_bfloat16 hh, ll;
            split_bf16(e0 * inv, hh, ll);
            *(__nv_bfloat16*)(smb + H_QHI + (row * QP + lane) * 2) = hh;
            *(__nv_bfloat16*)(smb + H_QLO + (row * QP + lane) * 2) = ll;
            split_bf16(e1 * inv, hh, ll);
            *(__nv_bfloat16*)(smb + H_QHI + (row * QP + lane + 32) * 2) = hh;
            *(__nv_bfloat16*)(smb + H_QLO + (row * QP + lane + 32) * 2) = ll;
            if (c2ok) {
                split_bf16(e2 * inv, hh, ll);
                *(__nv_bfloat16*)(smb + H_QHI + (row * QP + lane + 64) * 2) = hh;
                *(__nv_bfloat16*)(smb + H_QLO + (row * QP + lane + 64) * 2) = ll;
            } else if (lane + 64 < 80) {
                *(__nv_bfloat16*)(smb + H_QHI + (row * QP + lane + 64) * 2) = __float2bfloat16(0.f);
                *(__nv_bfloat16*)(smb + H_QLO + (row * QP + lane + 64) * 2) = __float2bfloat16(0.f);
            }
        }
    }
    __syncthreads();

    // ---- phase 3: TC AV; epilogue emits pre-split hi/lo bf16
    {
        const int b_rbase = warp_n * 32 + (q >> 1) * 8 + rr;
        float av[4][4];
#pragma unroll
        for (int j = 0; j < 4; j++)
#pragma unroll
            for (int t = 0; t < 4; t++) av[j][t] = 0.f;

#pragma unroll
        for (int kk = 0; kk < 5; kk++) {
            int kof = kk * 16;
            uint32_t afh[4], afl[4];
            ldm_x4(afh, sb + H_QHI + (a_r * QP + kof + a_k) * 2);
            ldm_x4(afl, sb + H_QLO + (a_r * QP + kof + a_k) * 2);
            uint32_t bfh[2][4], bfl[2][4];
#pragma unroll
            for (int ng = 0; ng < 2; ng++) {
                uint32_t bo = ((b_rbase + ng * 16) * VTP + kof + b_k) * 2;
                ldm_x4(bfh[ng], sb + H_VTHI + bo);
                ldm_x4(bfl[ng], sb + H_VTLO + bo);
            }
#pragma unroll
            for (int j = 0; j < 4; j++) {
                const int g = j >> 1, hs = (j & 1) * 2;
                mma16816(av[j], afh, bfh[g][hs], bfh[g][hs + 1]);
                mma16816(av[j], afh, bfl[g][hs], bfl[g][hs + 1]);
                mma16816(av[j], afl, bfh[g][hs], bfh[g][hs + 1]);
            }
        }

        size_t obase = ((size_t)n * GQ + qbase) * GD + h * GS;
#pragma unroll
        for (int j = 0; j < 4; j++) {
            int col = warp_n * 32 + j * 8 + ec;
            int row = warp_m * 16 + er;
            __nv_bfloat16 h0, l0, h1, l1;
            __nv_bfloat162 ph, pl;
            split_bf16(av[j][0], h0, l0);
            split_bf16(av[j][1], h1, l1);
            ph.x = h0; ph.y = h1; pl.x = l0; pl.y = l1;
            *(__nv_bfloat162*)(oghi + obase + (size_t)row * GD + col) = ph;
            *(__nv_bfloat162*)(oglo + obase + (size_t)row * GD + col) = pl;
            split_bf16(av[j][2], h0, l0);
            split_bf16(av[j][3], h1, l1);
            ph.x = h0; ph.y = h1; pl.x = l0; pl.y = l1;
            *(__nv_bfloat162*)(oghi + obase + (size_t)(row + 8) * GD + col) = ph;
            *(__nv_bfloat162*)(oglo + obase + (size_t)(row + 8) * GD + col) = pl;
        }
    }
}

// ---------------------------------------------------------------------------
// W[K][N] fp32 -> Wt[N][K] hi/lo bf16
__global__ void transpose_split(const float* __restrict__ W,
                                __nv_bfloat16* __restrict__ Whi,
                                __nv_bfloat16* __restrict__ Wlo, int K, int N)
{
    __shared__ float t[32][33];
    int k0 = blockIdx.y * 32, n0 = blockIdx.x * 32;
    int x = threadIdx.x, y = threadIdx.y;  // 32 x 8
#pragma unroll
    for (int i = 0; i < 32; i += 8) t[y + i][x] = W[(size_t)(k0 + y + i) * N + n0 + x];
    __syncthreads();
#pragma unroll
    for (int i = 0; i < 32; i += 8) {
        __nv_bfloat16 h, l;
        split_bf16(t[x][y + i], h, l);
        Whi[(size_t)(n0 + y + i) * K + k0 + x] = h;
        Wlo[(size_t)(n0 + y + i) * K + k0 + x] = l;
    }
}

// ---------------------------------------------------------------------------
extern "C" void kernel_launch(void* const* d_in, const int* in_sizes, int n_in,
                              void* d_out, int out_size)
{
    const float* query   = (const float*)d_in[0];
    const float* context = (const float*)d_in[1];
    const float* Wq      = (const float*)d_in[2];
    const float* Wk      = (const float*)d_in[3];
    const float* Wv      = (const float*)d_in[4];
    const float* Wo      = (const float*)d_in[5];
    const float* bo      = (const float*)d_in[6];
    float* out = (float*)d_out;

    void *pah, *pal, *pqh, *pql, *pkh, *pkl, *pvth, *pvtl, *pwqh, *pwql, *pwoh, *pwol;
    cudaGetSymbolAddress(&pah, g_atthi);
    cudaGetSymbolAddress(&pal, g_attlo);
    cudaGetSymbolAddress(&pqh, g_qhi);
    cudaGetSymbolAddress(&pql, g_qlo);
    cudaGetSymbolAddress(&pkh, g_khi);
    cudaGetSymbolAddress(&pkl, g_klo);
    cudaGetSymbolAddress(&pvth, g_vThi);
    cudaGetSymbolAddress(&pvtl, g_vTlo);
    cudaGetSymbolAddress(&pwqh, g_wqT_hi);
    cudaGetSymbolAddress(&pwql, g_wqT_lo);
    cudaGetSymbolAddress(&pwoh, g_woT_hi);
    cudaGetSymbolAddress(&pwol, g_woT_lo);

    cudaFuncSetAttribute((const void*)gemm_mma3f<false, true, false>,
                         cudaFuncAttributeMaxDynamicSharedMemorySize, GEMM_SMEM);
    cudaFuncSetAttribute((const void*)gemm_mma3f<true, false, true>,
                         cudaFuncAttributeMaxDynamicSharedMemorySize, GEMM_SMEM);
    cudaFuncSetAttribute((const void*)attn_tc,
                         cudaFuncAttributeMaxDynamicSharedMemorySize, H_SMEM);

    // prep
    {
        dim3 b(32, 8);
        transpose_split<<<dim3(GD / 32, GD / 32), b>>>(Wq, (__nv_bfloat16*)pwqh,
                                                       (__nv_bfloat16*)pwql, GD, GD);
        transpose_split<<<dim3(GD / 32, GD / 32), b>>>(Wo, (__nv_bfloat16*)pwoh,
                                                       (__nv_bfloat16*)pwol, GD, GD);
        zero_vt_pad<<<(GN * GH * 64 * 3 + 255) / 256, 256>>>(
            (__nv_bfloat16*)pvth, (__nv_bfloat16*)pvtl);
    }
    // K (split) + V (transposed split) projections fused
    {
        dim3 grid((GD / 64) * 2, (GN * GC + 63) / 64);
        sgemm64_dual<<<grid, 256>>>(context, Wk, Wv,
                                    (__nv_bfloat16*)pkh, (__nv_bfloat16*)pkl,
                                    (__nv_bfloat16*)pvth, (__nv_bfloat16*)pvtl,
                                    GN * GC, GD, GDC);
    }
    // Q projection: golden 256-thread gemm, fp32 A, split+scaled epilogue
    {
        dim3 grid(GD / 128, GM / 128);
        gemm_mma3f<false, true, false><<<grid, 256, GEMM_SMEM>>>(
            query, nullptr, nullptr,
            (const __nv_bfloat16*)pwqh, (const __nv_bfloat16*)pwql,
            nullptr, nullptr, (__nv_bfloat16*)pqh, (__nv_bfloat16*)pql,
            GM, GD, GD);
    }
    // attention: full TC, pre-split output
    {
        dim3 grid(GQ / 64, GH, GN);
        attn_tc<<<grid, 256, H_SMEM>>>(
            (const __nv_bfloat16*)pqh, (const __nv_bfloat16*)pql,
            (const __nv_bfloat16*)pkh, (const __nv_bfloat16*)pkl,
            (const __nv_bfloat16*)pvth, (const __nv_bfloat16*)pvtl,
            (__nv_bfloat16*)pah, (__nv_bfloat16*)pal);
    }
    // O projection + bias: golden gemm, A-presplit (pure cp.async loads)
    {
        dim3 grid(GD / 128, GM / 128);
        gemm_mma3f<true, false, true><<<grid, 256, GEMM_SMEM>>>(
            nullptr, (const __nv_bfloat16*)pah, (const __nv_bfloat16*)pal,
            (const __nv_bfloat16*)pwoh, (const __nv_bfloat16*)pwol,
            bo, out, nullptr, nullptr, GM, GD, GD);
    }
}

// round 16
// speedup vs baseline: 1.0345x; 1.0237x over previous
#include <cuda_runtime.h>
#include <cuda_bf16.h>
#include <cstdint>

#define GN 16
#define GQ 4096
#define GC 77
#define GD 512
#define GDC 768
#define GH 8
#define GS 64
#define GM (GN * GQ)  // 65536

// ---------------- scratch (device globals, allocation-free) ----------------
__device__ float g_att[(size_t)GM * GD];                 // attn output (fp32)
__device__ __nv_bfloat16 g_qhi[(size_t)GM * GD];         // q pre-split (scaled)
__device__ __nv_bfloat16 g_qlo[(size_t)GM * GD];
__device__ __nv_bfloat16 g_khi[(size_t)GN * GC * GD];    // k pre-split
__device__ __nv_bfloat16 g_klo[(size_t)GN * GC * GD];
__device__ __nv_bfloat16 g_vThi[(size_t)GN * GH * 64 * 80];  // V^T pre-split, c pad 80
__device__ __nv_bfloat16 g_vTlo[(size_t)GN * GH * 64 * 80];
__device__ __nv_bfloat16 g_wqT_hi[GD * GD], g_wqT_lo[GD * GD];
__device__ __nv_bfloat16 g_woT_hi[GD * GD], g_woT_lo[GD * GD];

__device__ __forceinline__ uint32_t smem_u32(const void* p) {
    uint32_t a;
    asm("{ .reg .u64 t; cvta.to.shared.u64 t, %1; cvt.u32.u64 %0, t; }"
        : "=r"(a) : "l"(p));
    return a;
}
__device__ __forceinline__ void cp_async16(uint32_t dst, const void* src) {
    asm volatile("cp.async.cg.shared.global [%0], [%1], 16;"
                 :: "r"(dst), "l"(src) : "memory");
}
#define CP_COMMIT() asm volatile("cp.async.commit_group;" ::: "memory")

__device__ __forceinline__ void ldm_x4(uint32_t (&f)[4], uint32_t addr) {
    asm volatile("ldmatrix.sync.aligned.m8n8.x4.shared.b16 {%0,%1,%2,%3}, [%4];"
                 : "=r"(f[0]), "=r"(f[1]), "=r"(f[2]), "=r"(f[3]) : "r"(addr));
}
__device__ __forceinline__ void mma16816(float (&d)[4], const uint32_t (&a)[4],
                                         uint32_t b0, uint32_t b1) {
    asm volatile(
        "mma.sync.aligned.m16n8k16.row.col.f32.bf16.bf16.f32 "
        "{%0,%1,%2,%3}, {%4,%5,%6,%7}, {%8,%9}, {%0,%1,%2,%3};"
        : "+f"(d[0]), "+f"(d[1]), "+f"(d[2]), "+f"(d[3])
        : "r"(a[0]), "r"(a[1]), "r"(a[2]), "r"(a[3]), "r"(b0), "r"(b1));
}

__device__ __forceinline__ void split_bf16(float x, __nv_bfloat16& hi, __nv_bfloat16& lo) {
    hi = __float2bfloat16_rn(x);
    lo = __float2bfloat16_rn(x - __bfloat162float(hi));
}

// ---------------------------------------------------------------------------
// bf16x3 mma.sync GEMM — R6/R13 GOLDEN 256-thread config, verbatim (FROZEN).
// BANNED (proven harmful): regrouped inner loop, launch_bounds minBlocks=2
// (R7-R9 corruption); 512-thread/32x32 warp tiles (R14 slower);
// A-presplit cp.async path + attn presplit output (R15 slower).
// ---------------------------------------------------------------------------
#define LDT 40
#define TILE_B (128 * LDT)
#define TILE_BYTES (TILE_B * 2)
#define STAGE_BYTES (4 * TILE_BYTES)
#define GEMM_SMEM (2 * STAGE_BYTES)   // 81920 B

template <bool HAS_BIAS, bool OUT_SPLIT>
__global__ __launch_bounds__(256) void gemm_mma3f(
    const float* __restrict__ A,
    const __nv_bfloat16* __restrict__ Bhi, const __nv_bfloat16* __restrict__ Blo,
    const float* __restrict__ bias, float* __restrict__ C,
    __nv_bfloat16* __restrict__ Chi, __nv_bfloat16* __restrict__ Clo,
    int M, int N, int K)
{
    extern __shared__ __align__(16) char gsm[];
    const uint32_t sa = smem_u32(gsm);

    const int tid = threadIdx.x;
    const int wid = tid >> 5, lane = tid & 31;
    const int warp_m = wid & 3;
    const int warp_n = wid >> 2;
    const int rowBase = blockIdx.y * 128;
    const int colBase = blockIdx.x * 128;

    const float* Ab = A + (size_t)rowBase * K;
    const size_t bOff = (size_t)colBase * K;

    const int ldr0 = tid >> 2, ldc0 = (tid & 3);
    const int ldr1 = (tid + 256) >> 2, ldc1 = (tid & 3);

    const int q = lane >> 3, r = lane & 7;
    const int a_row = warp_m * 32 + ((q & 1) * 8) + r;
    const int a_kof = (q >> 1) * 8;
    const int b_row = warp_n * 64 + ((q >> 1) * 8) + r;
    const int b_kof = (q & 1) * 8;

    float acc[2][8][4];
#pragma unroll
    for (int i = 0; i < 2; i++)
#pragma unroll
        for (int j = 0; j < 8; j++)
#pragma unroll
            for (int t = 0; t < 4; t++) acc[i][j][t] = 0.f;

    const int NC = K >> 5;

    float4 areg[4];
    auto ldg_A = [&](int c) {
        const int k0 = c << 5;
#pragma unroll
        for (int i = 0; i < 4; i++) {
            int ch = tid + i * 256;
            int row = ch >> 3, kc = (ch & 7) * 4;
            areg[i] = *(const float4*)(Ab + (size_t)row * K + k0 + kc);
        }
    };
    auto sts_A = [&](int c) {
        const uint32_t st = (c & 1) * STAGE_BYTES;
#pragma unroll
        for (int i = 0; i < 4; i++) {
            int ch = tid + i * 256;
            int row = ch >> 3, kc = (ch & 7) * 4;
            __nv_bfloat16 h[4], l[4];
            split_bf16(areg[i].x, h[0], l[0]);
            split_bf16(areg[i].y, h[1], l[1]);
            split_bf16(areg[i].z, h[2], l[2]);
            split_bf16(areg[i].w, h[3], l[3]);
            uint32_t off = (row * LDT + kc) * 2;
            *(uint2*)(gsm + st + off) = *(uint2*)h;
            *(uint2*)(gsm + st + TILE_BYTES + off) = *(uint2*)l;
        }
    };
    auto load_B = [&](int c) {
        const int k0 = c << 5;
        const uint32_t st = sa + (c & 1) * STAGE_BYTES;
        const uint32_t o0 = (ldr0 * LDT + ldc0 * 8) * 2;
        const uint32_t o1 = (ldr1 * LDT + ldc1 * 8) * 2;
        const size_t g0 = (size_t)ldr0 * K + k0 + ldc0 * 8;
        const size_t g1 = (size_t)ldr1 * K + k0 + ldc1 * 8;
        cp_async16(st + 2 * TILE_BYTES + o0, Bhi + bOff + g0);
        cp_async16(st + 2 * TILE_BYTES + o1, Bhi + bOff + g1);
        cp_async16(st + 3 * TILE_BYTES + o0, Blo + bOff + g0);
        cp_async16(st + 3 * TILE_BYTES + o1, Blo + bOff + g1);
        CP_COMMIT();
    };

    ldg_A(0);
    load_B(0);
    sts_A(0);

    for (int c = 0; c < NC; c++) {
        if (c + 1 < NC) {
            ldg_A(c + 1);
            load_B(c + 1);
            asm volatile("cp.async.wait_group 1;" ::: "memory");
        } else {
            asm volatile("cp.async.wait_group 0;" ::: "memory");
        }
        __syncthreads();

        const uint32_t st = sa + (c & 1) * STAGE_BYTES;
#pragma unroll
        for (int ks = 0; ks < 2; ks++) {
            uint32_t afh[2][4], afl[2][4];
#pragma unroll
            for (int i = 0; i < 2; i++) {
                uint32_t ao = ((a_row + i * 16) * LDT + ks * 16 + a_kof) * 2;
                ldm_x4(afh[i], st + ao);
                ldm_x4(afl[i], st + TILE_BYTES + ao);
            }
            uint32_t bfh[4][4], bfl[4][4];
#pragma unroll
            for (int ng = 0; ng < 4; ng++) {
                uint32_t bo = ((b_row + ng * 16) * LDT + ks * 16 + b_kof) * 2;
                ldm_x4(bfh[ng], st + 2 * TILE_BYTES + bo);
                ldm_x4(bfl[ng], st + 3 * TILE_BYTES + bo);
            }
#pragma unroll
            for (int i = 0; i < 2; i++)
#pragma unroll
                for (int j = 0; j < 8; j++) {
                    const int g = j >> 1, h = (j & 1) * 2;
                    mma16816(acc[i][j], afh[i], bfh[g][h], bfh[g][h + 1]);
                    mma16816(acc[i][j], afh[i], bfl[g][h], bfl[g][h + 1]);
                    mma16816(acc[i][j], afl[i], bfh[g][h], bfh[g][h + 1]);
                }
        }
        if (c + 1 < NC) sts_A(c + 1);
    }

    const int er = lane >> 2, ec = (lane & 3) * 2;
#pragma unroll
    for (int i = 0; i < 2; i++) {
#pragma unroll
        for (int j = 0; j < 8; j++) {
            int row0 = rowBase + warp_m * 32 + i * 16 + er;
            int col = colBase + warp_n * 64 + j * 8 + ec;
            if (OUT_SPLIT) {
                __nv_bfloat16 h0, l0, h1, l1;
                __nv_bfloat162 ph, pl;
                split_bf16(acc[i][j][0] * 0.125f, h0, l0);
                split_bf16(acc[i][j][1] * 0.125f, h1, l1);
                ph.x = h0; ph.y = h1; pl.x = l0; pl.y = l1;
                *(__nv_bfloat162*)(Chi + (size_t)row0 * N + col) = ph;
                *(__nv_bfloat162*)(Clo + (size_t)row0 * N + col) = pl;
                split_bf16(acc[i][j][2] * 0.125f, h0, l0);
                split_bf16(acc[i][j][3] * 0.125f, h1, l1);
                ph.x = h0; ph.y = h1; pl.x = l0; pl.y = l1;
                *(__nv_bfloat162*)(Chi + (size_t)(row0 + 8) * N + col) = ph;
                *(__nv_bfloat162*)(Clo + (size_t)(row0 + 8) * N + col) = pl;
            } else {
                float2 v0 = make_float2(acc[i][j][0], acc[i][j][1]);
                float2 v1 = make_float2(acc[i][j][2], acc[i][j][3]);
                if (HAS_BIAS) {
                    float2 bv = *(const float2*)(bias + col);
                    v0.x += bv.x; v0.y += bv.y;
                    v1.x += bv.x; v1.y += bv.y;
                }
                *(float2*)(C + (size_t)row0 * N + col) = v0;
                *(float2*)(C + (size_t)(row0 + 8) * N + col) = v1;
            }
        }
    }
}

// ---------------------------------------------------------------------------
// fp32 SGEMM 64x64, dual-B. Inner loop now uses float4 LDS (8->2 LDS per kk).
// First half: K -> split hi/lo bf16. Second half: V -> transposed split.
// ---------------------------------------------------------------------------
__global__ __launch_bounds__(256) void sgemm64_dual(
    const float* __restrict__ A,
    const float* __restrict__ B1, const float* __restrict__ B2,
    __nv_bfloat16* __restrict__ Khi, __nv_bfloat16* __restrict__ Klo,
    __nv_bfloat16* __restrict__ VThi, __nv_bfloat16* __restrict__ VTlo,
    int M, int N, int K)
{
    __shared__ __align__(16) float As[16][68];
    __shared__ __align__(16) float Bs[16][68];
    const int nb = N >> 6;
    const bool second = (int)blockIdx.x >= nb;
    const float* B = second ? B2 : B1;
    const int tid = threadIdx.x;
    const int rowBase = blockIdx.y * 64;
    const int colBase = (second ? blockIdx.x - nb : blockIdx.x) * 64;
    const int aRow = tid >> 2, aCol = (tid & 3) * 4;
    const int bRow = tid >> 4, bCol = (tid & 15) * 4;
    const int ty = tid >> 4, tx = tid & 15;

    float acc[4][4];
#pragma unroll
    for (int i = 0; i < 4; i++)
#pragma unroll
        for (int j = 0; j < 4; j++) acc[i][j] = 0.f;

    const bool aValid = (rowBase + aRow) < M;
    const float* Aptr = A + (size_t)(rowBase + aRow) * K + aCol;
    const float* Bptr = B + (size_t)bRow * N + colBase + bCol;

    for (int k0 = 0; k0 < K; k0 += 16) {
        float4 av = aValid ? *(const float4*)(Aptr + k0) : make_float4(0, 0, 0, 0);
        float4 bv = *(const float4*)(Bptr + (size_t)k0 * N);
        As[aCol + 0][aRow] = av.x; As[aCol + 1][aRow] = av.y;
        As[aCol + 2][aRow] = av.z; As[aCol + 3][aRow] = av.w;
        *(float4*)&Bs[bRow][bCol] = bv;
        __syncthreads();
#pragma unroll
        for (int kk = 0; kk < 16; kk++) {
            float4 a = *(const float4*)&As[kk][ty * 4];
            float4 b = *(const float4*)&Bs[kk][tx * 4];
            float ar[4] = {a.x, a.y, a.z, a.w};
            float br[4] = {b.x, b.y, b.z, b.w};
#pragma unroll
            for (int i = 0; i < 4; i++)
#pragma unroll
                for (int j = 0; j < 4; j++) acc[i][j] = fmaf(ar[i], br[j], acc[i][j]);
        }
        __syncthreads();
    }
#pragma unroll
    for (int i = 0; i < 4; i++) {
        int rr = rowBase + ty * 4 + i;
        if (rr >= M) continue;
        if (second) {
            int nIdx = rr / GC, cc = rr - nIdx * GC;
#pragma unroll
            for (int j = 0; j < 4; j++) {
                int s = colBase + tx * 4 + j;
                int hh = s >> 6, ss = s & 63;
                size_t o = (((size_t)(nIdx * GH + hh) * 64) + ss) * 80 + cc;
                __nv_bfloat16 h, l;
                split_bf16(acc[i][j], h, l);
                VThi[o] = h;
                VTlo[o] = l;
            }
        } else {
            __nv_bfloat16 h[4], l[4];
#pragma unroll
            for (int j = 0; j < 4; j++) split_bf16(acc[i][j], h[j], l[j]);
            __nv_bfloat162 p;
            size_t o = (size_t)rr * N + colBase + tx * 4;
            p.x = h[0]; p.y = h[1]; *(__nv_bfloat162*)(Khi + o) = p;
            p.x = h[2]; p.y = h[3]; *(__nv_bfloat162*)(Khi + o + 2) = p;
            p.x = l[0]; p.y = l[1]; *(__nv_bfloat162*)(Klo + o) = p;
            p.x = l[2]; p.y = l[3]; *(__nv_bfloat162*)(Klo + o + 2) = p;
        }
    }
}

// Zero the V^T pad columns c in [77,80) for all (n,h,s).
__global__ void zero_vt_pad(__nv_bfloat16* a, __nv_bfloat16* b)
{
    int i = blockIdx.x * blockDim.x + threadIdx.x;
    if (i >= GN * GH * 64 * 3) return;
    int c = 77 + (i % 3);
    int row = i / 3;
    a[(size_t)row * 80 + c] = __float2bfloat16(0.f);
    b[(size_t)row * 80 + c] = __float2bfloat16(0.f);
}

// ---------------------------------------------------------------------------
// TC attention (R13, verbatim): TC scores + TC AV (bf16x3), fp32 softmax,
// fp32 output.
// ---------------------------------------------------------------------------
#define QP 88
#define LDKK 72
#define VTP 88
#define H_QHI 0
#define H_QLO 11264
#define H_KHI 22528
#define H_KLO 36352
#define H_VTHI 50176
#define H_VTLO 61440
#define H_WS 72704
#define H_SMEM (H_WS + 64 * 80 * 4)   // 93184

__global__ __launch_bounds__(256) void attn_tc(
    const __nv_bfloat16* __restrict__ qhi, const __nv_bfloat16* __restrict__ qlo,
    const __nv_bfloat16* __restrict__ khi, const __nv_bfloat16* __restrict__ klo,
    const __nv_bfloat16* __restrict__ vthi, const __nv_bfloat16* __restrict__ vtlo,
    float* __restrict__ og)
{
    extern __shared__ __align__(16) char smb[];
    const uint32_t sb = smem_u32(smb);
    float* ws = (float*)(smb + H_WS);   // [64][80]

    const int n = blockIdx.z, h = blockIdx.y;
    const int qbase = blockIdx.x * 64;
    const int tid = threadIdx.x;
    const int wid = tid >> 5, lane = tid & 31;

    const size_t kOff = (size_t)n * GC * GD + h * GS;
    const size_t qOff = ((size_t)n * GQ + qbase) * GD + h * GS;
    const size_t vtOff = ((size_t)(n * GH + h) * 64) * 80;

    for (int i = tid; i < 19 * 32; i += 256) {
        int rr = 77 + (i >> 5), cc = (i & 31) * 2;
        *(uint32_t*)(smb + H_KHI + (rr * LDKK + cc) * 2) = 0;
        *(uint32_t*)(smb + H_KLO + (rr * LDKK + cc) * 2) = 0;
    }
    for (int i = tid; i < GC * 8; i += 256) {
        int c = i >> 3, ck = (i & 7) * 8;
        cp_async16(sb + H_KHI + (c * LDKK + ck) * 2, khi + kOff + (size_t)c * GD + ck);
        cp_async16(sb + H_KLO + (c * LDKK + ck) * 2, klo + kOff + (size_t)c * GD + ck);
    }
    for (int i = tid; i < 64 * 8; i += 256) {
        int rr = i >> 3, ck = (i & 7) * 8;
        cp_async16(sb + H_QHI + (rr * QP + ck) * 2, qhi + qOff + (size_t)rr * GD + ck);
        cp_async16(sb + H_QLO + (rr * QP + ck) * 2, qlo + qOff + (size_t)rr * GD + ck);
    }
    for (int i = tid; i < 64 * 10; i += 256) {
        int s = i / 10, ck = (i % 10) * 8;
        cp_async16(sb + H_VTHI + (s * VTP + ck) * 2, vthi + vtOff + (size_t)s * 80 + ck);
        cp_async16(sb + H_VTLO + (s * VTP + ck) * 2, vtlo + vtOff + (size_t)s * 80 + ck);
    }
    CP_COMMIT();
    asm volatile("cp.async.wait_group 0;" ::: "memory");
    __syncthreads();

    const int q = lane >> 3, rr = lane & 7;
    const int warp_m = wid & 3, warp_n = wid >> 2;
    const int a_r = warp_m * 16 + (q & 1) * 8 + rr;
    const int a_k = (q >> 1) * 8;
    const int b_k = (q & 1) * 8;
    const int er = lane >> 2, ec = (lane & 3) * 2;

    // ---- phase 1: TC scores
    {
        const int b_rbase = warp_n * 48 + (q >> 1) * 8 + rr;
        float sc[6][4];
#pragma unroll
        for (int j = 0; j < 6; j++)
#pragma unroll
            for (int t = 0; t < 4; t++) sc[j][t] = 0.f;

#pragma unroll
        for (int kk = 0; kk < 4; kk++) {
            int kof = kk * 16;
            uint32_t afh[4], afl[4];
            ldm_x4(afh, sb + H_QHI + (a_r * QP + kof + a_k) * 2);
            ldm_x4(afl, sb + H_QLO + (a_r * QP + kof + a_k) * 2);
            uint32_t bfh[3][4], bfl[3][4];
#pragma unroll
            for (int ng = 0; ng < 3; ng++) {
                uint32_t bo = ((b_rbase + ng * 16) * LDKK + kof + b_k) * 2;
                ldm_x4(bfh[ng], sb + H_KHI + bo);
                ldm_x4(bfl[ng], sb + H_KLO + bo);
            }
#pragma unroll
            for (int j = 0; j < 6; j++) {
                const int g = j >> 1, hs = (j & 1) * 2;
                mma16816(sc[j], afh, bfh[g][hs], bfh[g][hs + 1]);
                mma16816(sc[j], afh, bfl[g][hs], bfl[g][hs + 1]);
                mma16816(sc[j], afl, bfh[g][hs], bfh[g][hs + 1]);
            }
        }
#pragma unroll
        for (int j = 0; j < 6; j++) {
            int col = warp_n * 48 + j * 8 + ec;
            if (col < 80) {
                int row = warp_m * 16 + er;
                ws[row * 80 + col] = sc[j][0];
                ws[row * 80 + col + 1] = sc[j][1];
                ws[(row + 8) * 80 + col] = sc[j][2];
                ws[(row + 8) * 80 + col + 1] = sc[j][3];
            }
        }
    }
    __syncthreads();

    // ---- phase 2: softmax -> hi/lo weights into reused Q buffers
    {
        const int r0 = wid * 8;
        const bool c2ok = (lane < GC - 64);
#pragma unroll
        for (int r = 0; r < 8; r++) {
            int row = r0 + r;
            float s0 = ws[row * 80 + lane];
            float s1 = ws[row * 80 + lane + 32];
            float s2 = c2ok ? ws[row * 80 + lane + 64] : -1e30f;
            float m = fmaxf(fmaxf(s0, s1), s2);
#pragma unroll
            for (int o = 16; o; o >>= 1) m = fmaxf(m, __shfl_xor_sync(0xffffffffu, m, o));
            float e0 = __expf(s0 - m);
            float e1 = __expf(s1 - m);
            float e2 = c2ok ? __expf(s2 - m) : 0.f;
            float sum = e0 + e1 + e2;
#pragma unroll
            for (int o = 16; o; o >>= 1) sum += __shfl_xor_sync(0xffffffffu, sum, o);
            float inv = __frcp_rn(sum);
            __nv_bfloat16 hh, ll;
            split_bf16(e0 * inv, hh, ll);
            *(__nv_bfloat16*)(smb + H_QHI + (row * QP + lane) * 2) = hh;
            *(__nv_bfloat16*)(smb + H_QLO + (row * QP + lane) * 2) = ll;
            split_bf16(e1 * inv, hh, ll);
            *(__nv_bfloat16*)(smb + H_QHI + (row * QP + lane + 32) * 2) = hh;
            *(__nv_bfloat16*)(smb + H_QLO + (row * QP + lane + 32) * 2) = ll;
            if (c2ok) {
                split_bf16(e2 * inv, hh, ll);
                *(__nv_bfloat16*)(smb + H_QHI + (row * QP + lane + 64) * 2) = hh;
                *(__nv_bfloat16*)(smb + H_QLO + (row * QP + lane + 64) * 2) = ll;
            } else if (lane + 64 < 80) {
                *(__nv_bfloat16*)(smb + H_QHI + (row * QP + lane + 64) * 2) = __float2bfloat16(0.f);
                *(__nv_bfloat16*)(smb + H_QLO + (row * QP + lane + 64) * 2) = __float2bfloat16(0.f);
            }
        }
    }
    __syncthreads();

    // ---- phase 3: TC AV (fp32 float2 output — R13 epilogue)
    {
        const int b_rbase = warp_n * 32 + (q >> 1) * 8 + rr;
        float av[4][4];
#pragma unroll
        for (int j = 0; j < 4; j++)
#pragma unroll
            for (int t = 0; t < 4; t++) av[j][t] = 0.f;

#pragma unroll
        for (int kk = 0; kk < 5; kk++) {
            int kof = kk * 16;
            uint32_t afh[4], afl[4];
            ldm_x4(afh, sb + H_QHI + (a_r * QP + kof + a_k) * 2);
            ldm_x4(afl, sb + H_QLO + (a_r * QP + kof + a_k) * 2);
            uint32_t bfh[2][4], bfl[2][4];
#pragma unroll
            for (int ng = 0; ng < 2; ng++) {
                uint32_t bo = ((b_rbase + ng * 16) * VTP + kof + b_k) * 2;
                ldm_x4(bfh[ng], sb + H_VTHI + bo);
                ldm_x4(bfl[ng], sb + H_VTLO + bo);
            }
#pragma unroll
            for (int j = 0; j < 4; j++) {
                const int g = j >> 1, hs = (j & 1) * 2;
                mma16816(av[j], afh, bfh[g][hs], bfh[g][hs + 1]);
                mma16816(av[j], afh, bfl[g][hs], bfl[g][hs + 1]);
                mma16816(av[j], afl, bfh[g][hs], bfh[g][hs + 1]);
            }
        }

        float* ob = og + ((size_t)n * GQ + qbase) * GD + h * GS;
#pragma unroll
        for (int j = 0; j < 4; j++) {
            int col = warp_n * 32 + j * 8 + ec;
            int row = warp_m * 16 + er;
            *(float2*)(ob + (size_t)row * GD + col) = make_float2(av[j][0], av[j][1]);
            *(float2*)(ob + (size_t)(row + 8) * GD + col) = make_float2(av[j][2], av[j][3]);
        }
    }
}

// ---------------------------------------------------------------------------
// W[K][N] fp32 -> Wt[N][K] hi/lo bf16
__global__ void transpose_split(const float* __restrict__ W,
                                __nv_bfloat16* __restrict__ Whi,
                                __nv_bfloat16* __restrict__ Wlo, int K, int N)
{
    __shared__ float t[32][33];
    int k0 = blockIdx.y * 32, n0 = blockIdx.x * 32;
    int x = threadIdx.x, y = threadIdx.y;  // 32 x 8
#pragma unroll
    for (int i = 0; i < 32; i += 8) t[y + i][x] = W[(size_t)(k0 + y + i) * N + n0 + x];
    __syncthreads();
#pragma unroll
    for (int i = 0; i < 32; i += 8) {
        __nv_bfloat16 h, l;
        split_bf16(t[x][y + i], h, l);
        Whi[(size_t)(n0 + y + i) * K + k0 + x] = h;
        Wlo[(size_t)(n0 + y + i) * K + k0 + x] = l;
    }
}

// ---------------------------------------------------------------------------
extern "C" void kernel_launch(void* const* d_in, const int* in_sizes, int n_in,
                              void* d_out, int out_size)
{
    const float* query   = (const float*)d_in[0];
    const float* context = (const float*)d_in[1];
    const float* Wq      = (const float*)d_in[2];
    const float* Wk      = (const float*)d_in[3];
    const float* Wv      = (const float*)d_in[4];
    const float* Wo      = (const float*)d_in[5];
    const float* bo      = (const float*)d_in[6];
    float* out = (float*)d_out;

    void *pa, *pqh, *pql, *pkh, *pkl, *pvth, *pvtl, *pwqh, *pwql, *pwoh, *pwol;
    cudaGetSymbolAddress(&pa, g_att);
    cudaGetSymbolAddress(&pqh, g_qhi);
    cudaGetSymbolAddress(&pql, g_qlo);
    cudaGetSymbolAddress(&pkh, g_khi);
    cudaGetSymbolAddress(&pkl, g_klo);
    cudaGetSymbolAddress(&pvth, g_vThi);
    cudaGetSymbolAddress(&pvtl, g_vTlo);
    cudaGetSymbolAddress(&pwqh, g_wqT_hi);
    cudaGetSymbolAddress(&pwql, g_wqT_lo);
    cudaGetSymbolAddress(&pwoh, g_woT_hi);
    cudaGetSymbolAddress(&pwol, g_woT_lo);

    cudaFuncSetAttribute((const void*)gemm_mma3f<false, true>,
                         cudaFuncAttributeMaxDynamicSharedMemorySize, GEMM_SMEM);
    cudaFuncSetAttribute((const void*)gemm_mma3f<true, false>,
                         cudaFuncAttributeMaxDynamicSharedMemorySize, GEMM_SMEM);
    cudaFuncSetAttribute((const void*)attn_tc,
                         cudaFuncAttributeMaxDynamicSharedMemorySize, H_SMEM);

    // prep
    {
        dim3 b(32, 8);
        transpose_split<<<dim3(GD / 32, GD / 32), b>>>(Wq, (__nv_bfloat16*)pwqh,
                                                       (__nv_bfloat16*)pwql, GD, GD);
        transpose_split<<<dim3(GD / 32, GD / 32), b>>>(Wo, (__nv_bfloat16*)pwoh,
                                                       (__nv_bfloat16*)pwol, GD, GD);
        zero_vt_pad<<<(GN * GH * 64 * 3 + 255) / 256, 256>>>(
            (__nv_bfloat16*)pvth, (__nv_bfloat16*)pvtl);
    }
    // K (split) + V (transposed split) projections fused
    {
        dim3 grid((GD / 64) * 2, (GN * GC + 63) / 64);
        sgemm64_dual<<<grid, 256>>>(context, Wk, Wv,
                                    (__nv_bfloat16*)pkh, (__nv_bfloat16*)pkl,
                                    (__nv_bfloat16*)pvth, (__nv_bfloat16*)pvtl,
                                    GN * GC, GD, GDC);
    }
    // Q projection: golden 256-thread gemm, split+scaled epilogue
    {
        dim3 grid(GD / 128, GM / 128);
        gemm_mma3f<false, true><<<grid, 256, GEMM_SMEM>>>(
            query, (const __nv_bfloat16*)pwqh, (const __nv_bfloat16*)pwql,
            nullptr, nullptr, (__nv_bfloat16*)pqh, (__nv_bfloat16*)pql,
            GM, GD, GD);
    }
    // attention: full TC (R13)
    {
        dim3 grid(GQ / 64, GH, GN);
        attn_tc<<<grid, 256, H_SMEM>>>(
            (const __nv_bfloat16*)pqh, (const __nv_bfloat16*)pql,
            (const __nv_bfloat16*)pkh, (const __nv_bfloat16*)pkl,
            (const __nv_bfloat16*)pvth, (const __nv_bfloat16*)pvtl,
            (float*)pa);
    }
    // O projection + bias: golden gemm, fp32 A (in-kernel split)
    {
        dim3 grid(GD / 128, GM / 128);
        gemm_mma3f<true, false><<<grid, 256, GEMM_SMEM>>>(
            (const float*)pa, (const __nv_bfloat16*)pwoh, (const __nv_bfloat16*)pwol,
            bo, out, nullptr, nullptr, GM, GD, GD);
    }
}